// round 11
// baseline (speedup 1.0000x reference)
#include <cuda_runtime.h>

// BeamSearch_11295763988573 — GB300 (sm_103a)
//
// Output layout (float32, tuple flattened in order):
//   [0]                                   done        (1 elem)
//   [1, 1+B*N)                            new_mask    (B,N)
//   [1+B*N, 1+B*N+B*N*N)                  adj         (B,N,N)
//   then future_actions (B), present_time_new (B), step_mask (B)

static constexpr int B_ = 64;
static constexpr int N_ = 1024;
static constexpr int TI = 16;   // i-rows per block in adj kernel
static constexpr int BG = 4;    // b's per block in adj kernel

static constexpr long long OFF_NM  = 1;
static constexpr long long OFF_ADJ = 1 + (long long)B_ * N_;                 // 65537
static constexpr long long OFF_FA  = OFF_ADJ + (long long)B_ * N_ * N_;      // 67174401
static constexpr long long OFF_PT  = OFF_FA + B_;
static constexpr long long OFF_SM  = OFF_PT + B_;

// Per-(b,j) constants for the adj kernel: {closing, durat, dlast, new_mask}
__device__ float4 g_q[B_ * N_];
// Per-(b,i) constants: {fpresent, opening}
__device__ float2 g_fo[B_ * N_];

// ---------------------------------------------------------------------------
// Kernel 1: new_mask, fpresent, per-j constants, small outputs.
// Exact elementwise reproduction of the reference arithmetic.
// grid = (B, 4): blockIdx.y selects a 256-wide j slice.
// ---------------------------------------------------------------------------
__global__ __launch_bounds__(256) void bs_prep(
    const float4* __restrict__ inp4,   // (B,N,4): x=open, y=close, z=dur, w=ttime
    const float*  __restrict__ dist,   // (N,N)
    const float*  __restrict__ mask,   // (B,N)
    const float*  __restrict__ ptime,  // (B,1)
    const int*    __restrict__ pres,   // (B,)
    const int*    __restrict__ fut,    // (B,)
    float* __restrict__ out)
{
    const int b  = blockIdx.x;
    const int pa = pres[b];
    const float pt = ptime[b];
    const float tt0 = __ldg(reinterpret_cast<const float*>(inp4) + 3); // inputs[0,0,ARR]

    const int j = blockIdx.y * 256 + threadIdx.x;
    {
        const float4 in = inp4[b * N_ + j];
        const float arrive = __ldg(&dist[pa * N_ + j]) + pt;
        const float wait   = fmaxf(0.0f, in.x - arrive);
        const float s1     = arrive + wait;                 // arrive + wait (ref order)
        const float dl     = __ldg(&dist[j * N_ + (N_ - 1)]);
        const bool c1 = (s1 <= in.y);
        const bool c2 = (((s1 + in.z) + dl) <= tt0);        // ((arr+wait)+dur)+dlast <= tt
        float m = mask[b * N_ + j];
        if (j == pa) m = 0.0f;
        const float nm = (c1 && c2) ? m : 0.0f;

        out[OFF_NM + (long long)b * N_ + j] = nm;
        g_q [b * N_ + j] = make_float4(in.y, in.z, dl, nm);
        g_fo[b * N_ + j] = make_float2(s1 + in.z, in.x);    // fpresent, opening
    }

    if (threadIdx.x == 0 && blockIdx.y == 0) {
        const int fa = fut[b];
        const float4 infa = inp4[b * N_ + fa];
        const float arrj = __ldg(&dist[pa * N_ + fa]) + pt;
        const float wj   = fmaxf(0.0f, infa.x - arrj);
        out[OFF_FA + b] = (float)fa;
        out[OFF_PT + b] = (arrj + wj) + infa.z;
        out[OFF_SM + b] = 1.0f;
    }
}

// ---------------------------------------------------------------------------
// Kernel 2: adj (B,N,N). HBM-write-bound.
// adj[b,i,j] = (i==j) ? 1 : new_mask[b,j] * a1 * a2, with
//   arr2 = dist[i,j] + fpresent[b,i]
//   s    = fmax(arr2, open[b,i])       (outcome-exact vs arr2 + max(0, open-arr2))
//   a1   = s <= close[b,j]
//   a2   = ((s + dur[b,j]) + dlast[j]) <= ttime[b]
//
// Alignment: out base for adj is ≡ 4 bytes (mod 16), so thread t owns the
// ALIGNED output quad j∈[4t+3, 4t+7). dist for it = scalar d[4t+3] (L1-hit)
// + aligned quad [4t+4, 4t+8). Thread 255 handles stragglers {0,1,2,1023}.
// Stores use __stcs (streaming) so the 256MB write stream does not evict the
// small dist/q read sets from L2.
//
// Block (0,0) additionally computes done = !any(new_mask[:, -1] > 0) from
// g_q (written by bs_prep, prior kernel on the stream) — saves a launch.
// ---------------------------------------------------------------------------
__device__ __forceinline__ float adjval(float d, float fp, float opn,
                                        float4 q, float tt)
{
    const float arr2 = d + fp;
    const float s    = fmaxf(arr2, opn);
    const float s2   = (s + q.y) + q.z;
    return (s <= q.x && s2 <= tt) ? q.w : 0.0f;
}

__global__ __launch_bounds__(256) void bs_adj(
    const float* __restrict__ dist,
    const float* __restrict__ inpf,    // raw float view of inputs
    float* __restrict__ out)
{
    const int t   = threadIdx.x;            // 0..255
    const int ib0 = blockIdx.x * TI;
    const int b0  = blockIdx.y * BG;
    const bool main_thr = (t < 255);
    const int j0 = 4 * t + 3;               // first owned output column (t<255)

    // ---- done reduction (block-uniform guard; only block (0,0) enters) ----
    if (blockIdx.x == 0 && blockIdx.y == 0) {
        int v = 0;
        if (t < B_) v = (g_q[t * N_ + (N_ - 1)].w > 0.0f) ? 1 : 0;
        const int any = __syncthreads_or(v);
        if (t == 0) out[0] = any ? 0.0f : 1.0f;
    }

#pragma unroll
    for (int bb = 0; bb < BG; ++bb) {
        const int b = b0 + bb;
        const float tt = __ldg(inpf + (long long)b * N_ * 4 + 3);  // inputs[b,0,ARR]

        float4 q0, q1, q2, q3;
        if (main_thr) {
            q0 = g_q[b * N_ + j0];
            q1 = g_q[b * N_ + j0 + 1];
            q2 = g_q[b * N_ + j0 + 2];
            q3 = g_q[b * N_ + j0 + 3];
        } else {
            q0 = g_q[b * N_ + 0];
            q1 = g_q[b * N_ + 1];
            q2 = g_q[b * N_ + 2];
            q3 = g_q[b * N_ + N_ - 1];
        }

        float* __restrict__ orow_base = out + OFF_ADJ + (long long)b * N_ * N_;

#pragma unroll
        for (int ii = 0; ii < TI; ++ii) {
            const int i = ib0 + ii;
            const float2 fo = g_fo[b * N_ + i];
            const float fp = fo.x, opn = fo.y;
            const float* __restrict__ drow = dist + (long long)i * N_;

            if (main_thr) {
                const float4 dq = *reinterpret_cast<const float4*>(drow + j0 + 1);
                const float  d0 = __ldg(drow + j0);   // L1-hit, no cross-lane dep

                float v0 = adjval(d0,   fp, opn, q0, tt);
                float v1 = adjval(dq.x, fp, opn, q1, tt);
                float v2 = adjval(dq.y, fp, opn, q2, tt);
                float v3 = adjval(dq.z, fp, opn, q3, tt);

                const unsigned du = (unsigned)(i - j0);   // diagonal patch
                if (du < 4u) {
                    if      (du == 0u) v0 = 1.0f;
                    else if (du == 1u) v1 = 1.0f;
                    else if (du == 2u) v2 = 1.0f;
                    else               v3 = 1.0f;
                }
                __stcs(reinterpret_cast<float4*>(orow_base + (long long)i * N_ + j0),
                       make_float4(v0, v1, v2, v3));
            } else {
                // Straggler columns j = 0,1,2 and j = 1023
                const float4 dq = *reinterpret_cast<const float4*>(drow);  // d[0..3]
                const float  dl = __ldg(drow + (N_ - 1));

                float v0 = adjval(dq.x, fp, opn, q0, tt);
                float v1 = adjval(dq.y, fp, opn, q1, tt);
                float v2 = adjval(dq.z, fp, opn, q2, tt);
                float v3 = adjval(dl,   fp, opn, q3, tt);
                if (i == 0)      v0 = 1.0f;
                if (i == 1)      v1 = 1.0f;
                if (i == 2)      v2 = 1.0f;
                if (i == N_ - 1) v3 = 1.0f;
                float* ro = orow_base + (long long)i * N_;
                __stcs(ro,          v0);
                __stcs(ro + 1,      v1);
                __stcs(ro + 2,      v2);
                __stcs(ro + N_ - 1, v3);
            }
        }
    }
}

// ---------------------------------------------------------------------------
extern "C" void kernel_launch(void* const* d_in, const int* in_sizes, int n_in,
                              void* d_out, int out_size)
{
    (void)in_sizes; (void)n_in; (void)out_size;
    const float* inputs = (const float*)d_in[0];
    const float* dist   = (const float*)d_in[1];
    const float* mask   = (const float*)d_in[2];
    const float* ptime  = (const float*)d_in[3];
    const int*   pres   = (const int*)d_in[4];
    const int*   fut    = (const int*)d_in[5];
    float* out = (float*)d_out;

    bs_prep<<<dim3(B_, 4), 256>>>((const float4*)inputs, dist, mask, ptime, pres, fut, out);
    bs_adj<<<dim3(N_ / TI, B_ / BG), 256>>>(dist, inputs, out);
}

// round 12
// speedup vs baseline: 1.6224x; 1.6224x over previous
#include <cuda_runtime.h>

// BeamSearch_11295763988573 — GB300 (sm_103a)
//
// Output layout (float32, tuple flattened in order):
//   [0]                                   done        (1 elem)
//   [1, 1+B*N)                            new_mask    (B,N)
//   [1+B*N, 1+B*N+B*N*N)                  adj         (B,N,N)
//   then future_actions (B), present_time_new (B), step_mask (B)

static constexpr int B_ = 64;
static constexpr int N_ = 1024;
static constexpr int TI = 16;   // i-rows per block in adj kernel
static constexpr int NP = N_ + 4;  // padded row stride for g_q2 (16B-aligned pairs)

static constexpr long long OFF_NM  = 1;
static constexpr long long OFF_ADJ = 1 + (long long)B_ * N_;                 // 65537
static constexpr long long OFF_FA  = OFF_ADJ + (long long)B_ * N_ * N_;      // 67174401
static constexpr long long OFF_PT  = OFF_FA + B_;
static constexpr long long OFF_SM  = OFF_PT + B_;

// Per-(b,j) constants, PADDED BY ONE: row r, index j+1 holds {thr, nm} for
// column j. thr = min(close, X) where X is the exact largest float s with
// ((s+dur)+dlast) <= tt  =>  (s<=close && (s+dur)+dlast<=tt)  <=>  s<=thr.
// The +1 shift makes the quad owned by thread t (j0=4t+3) start at padded
// index 4t+4, i.e. 16B-aligned for float4 loads of two float2 pairs.
__device__ __align__(16) float2 g_q2[B_ * NP];
// Per-(b,i) constants: {fpresent, opening}
__device__ float2 g_fo[B_ * N_];

// ---------------------------------------------------------------------------
// Kernel 1: new_mask, fpresent, thresholds, small outputs.
// new_mask / c1 / c2 reproduce the reference arithmetic exactly.
// grid = (B, 4): blockIdx.y selects a 256-wide j slice.
// ---------------------------------------------------------------------------
__global__ __launch_bounds__(256) void bs_prep(
    const float4* __restrict__ inp4,   // (B,N,4): x=open, y=close, z=dur, w=ttime
    const float*  __restrict__ dist,   // (N,N)
    const float*  __restrict__ mask,   // (B,N)
    const float*  __restrict__ ptime,  // (B,1)
    const int*    __restrict__ pres,   // (B,)
    const int*    __restrict__ fut,    // (B,)
    float* __restrict__ out)
{
    const int b  = blockIdx.x;
    const int pa = pres[b];
    const float pt = ptime[b];
    const float tt0 = __ldg(reinterpret_cast<const float*>(inp4) + 3); // inputs[0,0,ARR]

    const int j = blockIdx.y * 256 + threadIdx.x;
    {
        const float4 in = inp4[b * N_ + j];
        const float arrive = __ldg(&dist[pa * N_ + j]) + pt;
        const float wait   = fmaxf(0.0f, in.x - arrive);
        const float s1     = arrive + wait;                 // arrive + wait (ref order)
        const float dl     = __ldg(&dist[j * N_ + (N_ - 1)]);
        const bool c1 = (s1 <= in.y);
        const bool c2 = (((s1 + in.z) + dl) <= tt0);        // ((arr+wait)+dur)+dlast <= tt
        float m = mask[b * N_ + j];
        if (j == pa) m = 0.0f;
        const float nm = (c1 && c2) ? m : 0.0f;

        out[OFF_NM + (long long)b * N_ + j] = nm;

        // Exact threshold X: largest float with ((X+dur)+dlast) <= tt0.
        // g(s) = (s+dur)+dlast is monotone nondecreasing, so the feasible set
        // is (-inf, X]. Seed with the approximate inverse, then bit-step.
        // Values are positive (~185..200) so integer bit-steps are ordered.
        float x = (tt0 - in.z) - dl;
        while (((x + in.z) + dl) > tt0)
            x = __int_as_float(__float_as_int(x) - 1);
        for (;;) {
            const float xn = __int_as_float(__float_as_int(x) + 1);
            if (((xn + in.z) + dl) <= tt0) x = xn; else break;
        }
        const float thr = fminf(in.y, x);

        g_q2[b * NP + j + 1] = make_float2(thr, nm);
        g_fo[b * N_ + j]     = make_float2(s1 + in.z, in.x);  // fpresent, opening
    }

    if (threadIdx.x == 0 && blockIdx.y == 0) {
        const int fa = fut[b];
        const float4 infa = inp4[b * N_ + fa];
        const float arrj = __ldg(&dist[pa * N_ + fa]) + pt;
        const float wj   = fmaxf(0.0f, infa.x - arrj);
        out[OFF_FA + b] = (float)fa;
        out[OFF_PT + b] = (arrj + wj) + infa.z;
        out[OFF_SM + b] = 1.0f;
    }
}

// ---------------------------------------------------------------------------
// Kernel 2: adj (B,N,N). HBM-write-bound target.
// adj[b,i,j] = (i==j) ? 1 : (fmax(dist[i,j]+fp, opn) <= thr[b,j]) ? nm[b,j] : 0
//   (fmax form is comparison-outcome-identical to arr2+max(0,opn-arr2);
//    verified rel_err == 0.0 in prior rounds.)
//
// Alignment: adj base is ≡ 4 bytes (mod 16); thread t owns the ALIGNED output
// quad j∈[4t+3, 4t+7). dist comes from the aligned quad [4t+4,4t+8) plus
// d[4t+3] via __shfl_up (warp-edge lanes do one scalar LDG). Thread 255
// handles straggler columns {0,1,2,1023} (its shfl value IS d[1023]).
// Streaming stores keep the 256MB write stream out of L2's read set.
// grid = (N/TI, B): one b per block, 27.7 blocks per SM residency slot.
// ---------------------------------------------------------------------------
__device__ __forceinline__ float adjval2(float d, float fp, float opn,
                                         float thr, float nm)
{
    const float s = fmaxf(d + fp, opn);
    return (s <= thr) ? nm : 0.0f;
}

__global__ __launch_bounds__(256, 6) void bs_adj(
    const float* __restrict__ dist,
    float* __restrict__ out)
{
    const int t   = threadIdx.x;            // 0..255
    const int ib0 = blockIdx.x * TI;
    const int b   = blockIdx.y;
    const bool main_thr = (t < 255);
    const int j0 = 4 * t + 3;               // first owned output column (t<255)

    // ---- done = !any(new_mask[:, -1] > 0); block-uniform guard ----
    if (blockIdx.x == 0 && blockIdx.y == 0) {
        int v = 0;
        if (t < B_) v = (g_q2[t * NP + 1024].y > 0.0f) ? 1 : 0;  // nm[b,1023]
        const int any = __syncthreads_or(v);
        if (t == 0) out[0] = any ? 0.0f : 1.0f;
    }

    const float2* __restrict__ qrow = g_q2 + b * NP;
    float thr0, nm0, thr1, nm1, thr2, nm2, thr3, nm3;
    if (main_thr) {
        const float4 qa = *reinterpret_cast<const float4*>(qrow + (j0 + 1));  // j0, j0+1
        const float4 qb = *reinterpret_cast<const float4*>(qrow + (j0 + 3));  // j0+2, j0+3
        thr0 = qa.x; nm0 = qa.y;  thr1 = qa.z; nm1 = qa.w;
        thr2 = qb.x; nm2 = qb.y;  thr3 = qb.z; nm3 = qb.w;
    } else {
        const float2 qa = qrow[1];     // j = 0
        const float2 qb = qrow[2];     // j = 1
        const float2 qc = qrow[3];     // j = 2
        const float2 qd = qrow[1024];  // j = 1023
        thr0 = qa.x; nm0 = qa.y;  thr1 = qb.x; nm1 = qb.y;
        thr2 = qc.x; nm2 = qc.y;  thr3 = qd.x; nm3 = qd.y;
    }

    float* __restrict__ orow_base = out + OFF_ADJ + (long long)b * N_ * N_;

#pragma unroll 4
    for (int ii = 0; ii < TI; ++ii) {
        const int i = ib0 + ii;
        const float2 fo = g_fo[b * N_ + i];
        const float fp = fo.x, opn = fo.y;
        const float* __restrict__ drow = dist + (long long)i * N_;

        float4 dq;
        if (main_thr) {
            dq = *reinterpret_cast<const float4*>(drow + j0 + 1);   // [4t+4, 4t+8)
        } else {
            dq = *reinterpret_cast<const float4*>(drow);            // d[0..3]
        }
        // d[4t+3] is the previous lane's dq.w; lane31's value IS d[1023]
        // from the perspective of thread 255.
        float dprev = __shfl_up_sync(0xFFFFFFFFu, dq.w, 1);

        if (main_thr) {
            if ((t & 31) == 0)  // warp-edge lane: fetch d[4t+3] directly
                dprev = __ldg(drow + j0);

            float v0 = adjval2(dprev, fp, opn, thr0, nm0);
            float v1 = adjval2(dq.x,  fp, opn, thr1, nm1);
            float v2 = adjval2(dq.y,  fp, opn, thr2, nm2);
            float v3 = adjval2(dq.z,  fp, opn, thr3, nm3);

            const unsigned du = (unsigned)(i - j0);   // diagonal patch
            if (du < 4u) {
                if      (du == 0u) v0 = 1.0f;
                else if (du == 1u) v1 = 1.0f;
                else if (du == 2u) v2 = 1.0f;
                else               v3 = 1.0f;
            }
            __stcs(reinterpret_cast<float4*>(orow_base + (long long)i * N_ + j0),
                   make_float4(v0, v1, v2, v3));
        } else {
            // Straggler columns j = 0,1,2 (dq.x/y/z) and j = 1023 (dprev)
            float v0 = adjval2(dq.x,  fp, opn, thr0, nm0);
            float v1 = adjval2(dq.y,  fp, opn, thr1, nm1);
            float v2 = adjval2(dq.z,  fp, opn, thr2, nm2);
            float v3 = adjval2(dprev, fp, opn, thr3, nm3);
            if (i == 0)      v0 = 1.0f;
            if (i == 1)      v1 = 1.0f;
            if (i == 2)      v2 = 1.0f;
            if (i == N_ - 1) v3 = 1.0f;
            float* ro = orow_base + (long long)i * N_;
            __stcs(ro,          v0);
            __stcs(ro + 1,      v1);
            __stcs(ro + 2,      v2);
            __stcs(ro + N_ - 1, v3);
        }
    }
}

// ---------------------------------------------------------------------------
extern "C" void kernel_launch(void* const* d_in, const int* in_sizes, int n_in,
                              void* d_out, int out_size)
{
    (void)in_sizes; (void)n_in; (void)out_size;
    const float* inputs = (const float*)d_in[0];
    const float* dist   = (const float*)d_in[1];
    const float* mask   = (const float*)d_in[2];
    const float* ptime  = (const float*)d_in[3];
    const int*   pres   = (const int*)d_in[4];
    const int*   fut    = (const int*)d_in[5];
    float* out = (float*)d_out;

    bs_prep<<<dim3(B_, 4), 256>>>((const float4*)inputs, dist, mask, ptime, pres, fut, out);
    bs_adj<<<dim3(N_ / TI, B_), 256>>>(dist, out);
}

// round 13
// speedup vs baseline: 1.7152x; 1.0572x over previous
#include <cuda_runtime.h>

// BeamSearch_11295763988573 — GB300 (sm_103a)
//
// Output layout (float32, tuple flattened in order):
//   [0]                                   done        (1 elem)
//   [1, 1+B*N)                            new_mask    (B,N)
//   [1+B*N, 1+B*N+B*N*N)                  adj         (B,N,N)
//   then future_actions (B), present_time_new (B), step_mask (B)

static constexpr int B_ = 64;
static constexpr int N_ = 1024;
static constexpr int TI = 8;      // i-rows per block in adj kernel
static constexpr int BG = 2;      // b's per block: one dist load feeds BG stores
static constexpr int NP = N_ + 4; // padded row stride for g_q2 (16B-aligned pairs)

static constexpr long long OFF_NM  = 1;
static constexpr long long OFF_ADJ = 1 + (long long)B_ * N_;                 // 65537
static constexpr long long OFF_FA  = OFF_ADJ + (long long)B_ * N_ * N_;      // 67174401
static constexpr long long OFF_PT  = OFF_FA + B_;
static constexpr long long OFF_SM  = OFF_PT + B_;

// Per-(b,j) constants, PADDED BY ONE: row b, index j+1 holds {thr, nm} for
// column j. thr = min(close, X) where X is the exact largest float s with
// ((s+dur)+dlast) <= tt  =>  (s<=close && (s+dur)+dlast<=tt)  <=>  s<=thr.
// The +1 shift makes the quad owned by thread t (j0=4t+3) start at padded
// index 4t+4, i.e. 16B-aligned for float4 loads of two float2 pairs.
__device__ __align__(16) float2 g_q2[B_ * NP];
// Per-(b,i) constants: {fpresent, opening}
__device__ float2 g_fo[B_ * N_];

// ---------------------------------------------------------------------------
// Kernel 1: new_mask, fpresent, thresholds, small outputs.
// new_mask / c1 / c2 reproduce the reference arithmetic exactly.
// grid = (B, 4): blockIdx.y selects a 256-wide j slice.
// ---------------------------------------------------------------------------
__global__ __launch_bounds__(256) void bs_prep(
    const float4* __restrict__ inp4,   // (B,N,4): x=open, y=close, z=dur, w=ttime
    const float*  __restrict__ dist,   // (N,N)
    const float*  __restrict__ mask,   // (B,N)
    const float*  __restrict__ ptime,  // (B,1)
    const int*    __restrict__ pres,   // (B,)
    const int*    __restrict__ fut,    // (B,)
    float* __restrict__ out)
{
    const int b  = blockIdx.x;
    const int pa = pres[b];
    const float pt = ptime[b];
    const float tt0 = __ldg(reinterpret_cast<const float*>(inp4) + 3); // inputs[0,0,ARR]

    const int j = blockIdx.y * 256 + threadIdx.x;
    {
        const float4 in = inp4[b * N_ + j];
        const float arrive = __ldg(&dist[pa * N_ + j]) + pt;
        const float wait   = fmaxf(0.0f, in.x - arrive);
        const float s1     = arrive + wait;                 // arrive + wait (ref order)
        const float dl     = __ldg(&dist[j * N_ + (N_ - 1)]);
        const bool c1 = (s1 <= in.y);
        const bool c2 = (((s1 + in.z) + dl) <= tt0);        // ((arr+wait)+dur)+dlast <= tt
        float m = mask[b * N_ + j];
        if (j == pa) m = 0.0f;
        const float nm = (c1 && c2) ? m : 0.0f;

        out[OFF_NM + (long long)b * N_ + j] = nm;

        // Exact threshold X: largest float with ((X+dur)+dlast) <= tt0.
        // g(s) = (s+dur)+dlast is monotone nondecreasing, so the feasible set
        // is (-inf, X]. Seed with the approximate inverse, then bit-step.
        // Values are positive (~185..200) so integer bit-steps are ordered.
        float x = (tt0 - in.z) - dl;
        while (((x + in.z) + dl) > tt0)
            x = __int_as_float(__float_as_int(x) - 1);
        for (;;) {
            const float xn = __int_as_float(__float_as_int(x) + 1);
            if (((xn + in.z) + dl) <= tt0) x = xn; else break;
        }
        const float thr = fminf(in.y, x);

        g_q2[b * NP + j + 1] = make_float2(thr, nm);
        g_fo[b * N_ + j]     = make_float2(s1 + in.z, in.x);  // fpresent, opening
    }

    if (threadIdx.x == 0 && blockIdx.y == 0) {
        const int fa = fut[b];
        const float4 infa = inp4[b * N_ + fa];
        const float arrj = __ldg(&dist[pa * N_ + fa]) + pt;
        const float wj   = fmaxf(0.0f, infa.x - arrj);
        out[OFF_FA + b] = (float)fa;
        out[OFF_PT + b] = (arrj + wj) + infa.z;
        out[OFF_SM + b] = 1.0f;
    }
}

// ---------------------------------------------------------------------------
// Kernel 2: adj (B,N,N). HBM-write-bound target.
// adj[b,i,j] = (i==j) ? 1 : (fmax(dist[i,j]+fp, opn) <= thr[b,j]) ? nm[b,j] : 0
//   (fmax form is comparison-outcome-identical to arr2+max(0,opn-arr2);
//    verified rel_err == 0.0 across prior rounds.)
//
// Alignment: adj base is ≡ 4 bytes (mod 16); thread t owns the ALIGNED output
// quad j∈[4t+3, 4t+7). dist comes from the aligned quad [4t+4,4t+8) plus
// d[4t+3] via __shfl_up (warp-edge lanes do one scalar LDG). Thread 255
// handles straggler columns {0,1,2,1023} (its shfl value IS d[1023]).
//
// BG=2: each dist quad + shfl feeds TWO batches' stores — halves read
// wavefronts per byte stored. Streaming stores keep the 256MB write stream
// out of L2's read set. grid = (N/TI, B/BG) = (128, 32) = 4096 blocks.
// ---------------------------------------------------------------------------
__device__ __forceinline__ float adjval2(float d, float fp, float opn,
                                         float thr, float nm)
{
    const float s = fmaxf(d + fp, opn);
    return (s <= thr) ? nm : 0.0f;
}

__global__ __launch_bounds__(256, 5) void bs_adj(
    const float* __restrict__ dist,
    float* __restrict__ out)
{
    const int t   = threadIdx.x;            // 0..255
    const int ib0 = blockIdx.x * TI;
    const int b0  = blockIdx.y * BG;
    const int b1  = b0 + 1;
    const bool main_thr = (t < 255);
    const int j0 = 4 * t + 3;               // first owned output column (t<255)

    // ---- done = !any(new_mask[:, -1] > 0); block-uniform guard ----
    if (blockIdx.x == 0 && blockIdx.y == 0) {
        int v = 0;
        if (t < B_) v = (g_q2[t * NP + 1024].y > 0.0f) ? 1 : 0;  // nm[b,1023]
        const int any = __syncthreads_or(v);
        if (t == 0) out[0] = any ? 0.0f : 1.0f;
    }

    // Hoist per-(b,j) constants for both batches.
    float thrA0, nmA0, thrA1, nmA1, thrA2, nmA2, thrA3, nmA3;
    float thrB0, nmB0, thrB1, nmB1, thrB2, nmB2, thrB3, nmB3;
    {
        const float2* __restrict__ qa = g_q2 + b0 * NP;
        const float2* __restrict__ qb = g_q2 + b1 * NP;
        if (main_thr) {
            const float4 a0 = *reinterpret_cast<const float4*>(qa + (j0 + 1));
            const float4 a1 = *reinterpret_cast<const float4*>(qa + (j0 + 3));
            const float4 c0 = *reinterpret_cast<const float4*>(qb + (j0 + 1));
            const float4 c1 = *reinterpret_cast<const float4*>(qb + (j0 + 3));
            thrA0 = a0.x; nmA0 = a0.y;  thrA1 = a0.z; nmA1 = a0.w;
            thrA2 = a1.x; nmA2 = a1.y;  thrA3 = a1.z; nmA3 = a1.w;
            thrB0 = c0.x; nmB0 = c0.y;  thrB1 = c0.z; nmB1 = c0.w;
            thrB2 = c1.x; nmB2 = c1.y;  thrB3 = c1.z; nmB3 = c1.w;
        } else {
            float2 p;
            p = qa[1];    thrA0 = p.x; nmA0 = p.y;   // j=0
            p = qa[2];    thrA1 = p.x; nmA1 = p.y;   // j=1
            p = qa[3];    thrA2 = p.x; nmA2 = p.y;   // j=2
            p = qa[1024]; thrA3 = p.x; nmA3 = p.y;   // j=1023
            p = qb[1];    thrB0 = p.x; nmB0 = p.y;
            p = qb[2];    thrB1 = p.x; nmB1 = p.y;
            p = qb[3];    thrB2 = p.x; nmB2 = p.y;
            p = qb[1024]; thrB3 = p.x; nmB3 = p.y;
        }
    }

    float* __restrict__ orowA = out + OFF_ADJ + (long long)b0 * N_ * N_;
    float* __restrict__ orowB = out + OFF_ADJ + (long long)b1 * N_ * N_;

#pragma unroll 4
    for (int ii = 0; ii < TI; ++ii) {
        const int i = ib0 + ii;
        const float2 foA = g_fo[b0 * N_ + i];
        const float2 foB = g_fo[b1 * N_ + i];
        const float fpA = foA.x, opA = foA.y;
        const float fpB = foB.x, opB = foB.y;
        const float* __restrict__ drow = dist + (long long)i * N_;

        float4 dq;
        if (main_thr) {
            dq = *reinterpret_cast<const float4*>(drow + j0 + 1);   // [4t+4, 4t+8)
        } else {
            dq = *reinterpret_cast<const float4*>(drow);            // d[0..3]
        }
        // d[4t+3] is the previous lane's dq.w; lane31's value IS d[1023]
        // from the perspective of thread 255.
        float dprev = __shfl_up_sync(0xFFFFFFFFu, dq.w, 1);

        if (main_thr) {
            if ((t & 31) == 0)  // warp-edge lane: fetch d[4t+3] directly
                dprev = __ldg(drow + j0);

            float a0 = adjval2(dprev, fpA, opA, thrA0, nmA0);
            float a1 = adjval2(dq.x,  fpA, opA, thrA1, nmA1);
            float a2 = adjval2(dq.y,  fpA, opA, thrA2, nmA2);
            float a3 = adjval2(dq.z,  fpA, opA, thrA3, nmA3);
            float c0 = adjval2(dprev, fpB, opB, thrB0, nmB0);
            float c1 = adjval2(dq.x,  fpB, opB, thrB1, nmB1);
            float c2 = adjval2(dq.y,  fpB, opB, thrB2, nmB2);
            float c3 = adjval2(dq.z,  fpB, opB, thrB3, nmB3);

            const unsigned du = (unsigned)(i - j0);   // diagonal patch (same j-map for both b)
            if (du < 4u) {
                if      (du == 0u) { a0 = 1.0f; c0 = 1.0f; }
                else if (du == 1u) { a1 = 1.0f; c1 = 1.0f; }
                else if (du == 2u) { a2 = 1.0f; c2 = 1.0f; }
                else               { a3 = 1.0f; c3 = 1.0f; }
            }
            __stcs(reinterpret_cast<float4*>(orowA + (long long)i * N_ + j0),
                   make_float4(a0, a1, a2, a3));
            __stcs(reinterpret_cast<float4*>(orowB + (long long)i * N_ + j0),
                   make_float4(c0, c1, c2, c3));
        } else {
            // Straggler columns j = 0,1,2 (dq.x/y/z) and j = 1023 (dprev)
            float a0 = adjval2(dq.x,  fpA, opA, thrA0, nmA0);
            float a1 = adjval2(dq.y,  fpA, opA, thrA1, nmA1);
            float a2 = adjval2(dq.z,  fpA, opA, thrA2, nmA2);
            float a3 = adjval2(dprev, fpA, opA, thrA3, nmA3);
            float c0 = adjval2(dq.x,  fpB, opB, thrB0, nmB0);
            float c1 = adjval2(dq.y,  fpB, opB, thrB1, nmB1);
            float c2 = adjval2(dq.z,  fpB, opB, thrB2, nmB2);
            float c3 = adjval2(dprev, fpB, opB, thrB3, nmB3);
            if (i == 0)      { a0 = 1.0f; c0 = 1.0f; }
            if (i == 1)      { a1 = 1.0f; c1 = 1.0f; }
            if (i == 2)      { a2 = 1.0f; c2 = 1.0f; }
            if (i == N_ - 1) { a3 = 1.0f; c3 = 1.0f; }
            float* rA = orowA + (long long)i * N_;
            float* rB = orowB + (long long)i * N_;
            __stcs(rA,          a0);
            __stcs(rA + 1,      a1);
            __stcs(rA + 2,      a2);
            __stcs(rA + N_ - 1, a3);
            __stcs(rB,          c0);
            __stcs(rB + 1,      c1);
            __stcs(rB + 2,      c2);
            __stcs(rB + N_ - 1, c3);
        }
    }
}

// ---------------------------------------------------------------------------
extern "C" void kernel_launch(void* const* d_in, const int* in_sizes, int n_in,
                              void* d_out, int out_size)
{
    (void)in_sizes; (void)n_in; (void)out_size;
    const float* inputs = (const float*)d_in[0];
    const float* dist   = (const float*)d_in[1];
    const float* mask   = (const float*)d_in[2];
    const float* ptime  = (const float*)d_in[3];
    const int*   pres   = (const int*)d_in[4];
    const int*   fut    = (const int*)d_in[5];
    float* out = (float*)d_out;

    bs_prep<<<dim3(B_, 4), 256>>>((const float4*)inputs, dist, mask, ptime, pres, fut, out);
    bs_adj<<<dim3(N_ / TI, B_ / BG), 256>>>(dist, out);
}